// round 15
// baseline (speedup 1.0000x reference)
#include <cuda_runtime.h>
#include <cstdint>

#define N_NODES 8192
#define D_IN    512
#define D_OUT   128
#define LEAKY   0.2f
#define MAX_E   512
#define NB_GEMM  128    // GEMM blocks (64 rows each); they become scanners after
#define NB_TOTAL 296    // 2 blocks/SM x 148 SMs: exactly one resident wave
#define S_DEPTH  3      // TMA ring depth (rows in flight per block)
#define ROW_BYTES 32768 // one adjacency row = 8192 floats
#define SEG_CAP  64     // per-warp staging slots (mean ~4 edges/warp)
#define DEF_CAP  96     // deferred-row list capacity

// Dynamic smem layout (GEMM tiles union the same pool)
#define OFF_STAGE (S_DEPTH * ROW_BYTES)            // 98304: stage[8][64] ints
#define OFF_CTL   (OFF_STAGE + 8 * SEG_CAP * 4)    // ints: wcnt[8] base[8] row[3] gdone ndef tot
#define OFF_DEF   (OFF_CTL + 128)                  // s_defer[DEF_CAP]
#define OFF_PART  (OFF_DEF + DEF_CAP * 4)          // s_part[8][128] floats
#define OFF_Z     (OFF_PART + 4096)                // s_Z[8]
#define OFF_MBAR  (OFF_Z + 64)
#define SMEM_TOTAL (OFF_MBAR + 64)                 // ~105 KB; 2 blocks/SM fits 228 KB

// ctl indices
#define CTL_WCNT  0
#define CTL_BASE  8
#define CTL_ROW   16
#define CTL_GDONE 19
#define CTL_NDEF  20
#define CTL_TOT   21

// Scratch (allocation-free: __device__ globals)
__device__ float g_h[N_NODES * D_OUT];        // 4 MB
__device__ float g_as[N_NODES];
__device__ float g_an[N_NODES];
__device__ int   g_edges[N_NODES * MAX_E];    // edge lists (deferred rows only)
__device__ int   g_cnt[N_NODES];
__device__ int   g_next;                      // dynamic row counter
__device__ int   g_done;                      // GEMM completion counter
__device__ int   g_fin;                       // block completion counter

// Packed dual-fp32 FMA (PTX f32x2, sm_100+): 2 FMAs per issue slot.
__device__ __forceinline__ void ffma2(float2& c, float2 a, float2 b) {
    asm("fma.rn.f32x2 %0, %1, %2, %0;"
        : "+l"(reinterpret_cast<unsigned long long&>(c))
        : "l"(reinterpret_cast<unsigned long long&>(a)),
          "l"(reinterpret_cast<unsigned long long&>(b)));
}

__device__ __forceinline__ uint32_t smem_u32(const void* p) {
    uint32_t a;
    asm("{ .reg .u64 t; cvta.to.shared.u64 t, %1; cvt.u32.u64 %0, t; }" : "=r"(a) : "l"(p));
    return a;
}

__device__ __forceinline__ void mbar_wait(uint32_t mbar, uint32_t phase) {
    asm volatile(
        "{\n\t"
        ".reg .pred P;\n\t"
        "W_%=:\n\t"
        "mbarrier.try_wait.parity.acquire.cta.shared::cta.b64 P, [%0], %1, 0x989680;\n\t"
        "@P bra D_%=;\n\t"
        "bra W_%=;\n\t"
        "D_%=:\n\t"
        "}"
        :: "r"(mbar), "r"(phase) : "memory");
}

// ---------------------------------------------------------------------------
// Warp-level row aggregation from a lane-indexed edge source.
// Lanes compute up to 32 softmax weights in parallel, then shuffle-broadcast
// (j,p) while all lanes gather h[j] float4 (512B coalesced, L2). No max-sub:
// logits are O(10), fp32-safe; non-edges contribute exactly 0 in fp32 so
// edge-only softmax == dense reference.
// Returns warp-partial (acc,Z); caller decides combine/write.
// ---------------------------------------------------------------------------
template <typename GetJ>
__device__ __forceinline__ void warp_row_partial(
    int cnt, float a_si, GetJ getj, int lane, float4& accO, float& ZO)
{
    float4 acc = make_float4(0.f, 0.f, 0.f, 0.f);
    float  Z   = 0.f;
    for (int b0 = 0; b0 < cnt; b0 += 32) {
        int   myj = 0;
        float p   = 0.f;
        const int k = b0 + lane;
        if (k < cnt) {
            myj = getj(k);
            float e = a_si + g_an[myj];
            e = (e >= 0.f) ? e : LEAKY * e;
            p = __expf(e);
        }
        Z += p;
        const int m  = min(32, cnt - b0);
        const int mp = (m + 3) & ~3;             // pad to 4; padded lanes p=0
        for (int k0 = 0; k0 < mp; k0 += 4) {
            #pragma unroll
            for (int u = 0; u < 4; u++) {
                const int   j  = __shfl_sync(0xffffffffu, myj, k0 + u);
                const float pk = __shfl_sync(0xffffffffu, p,   k0 + u);
                const float4 hv = *reinterpret_cast<const float4*>(
                    &g_h[(size_t)j * D_OUT + lane * 4]);
                acc.x += pk * hv.x; acc.y += pk * hv.y;
                acc.z += pk * hv.z; acc.w += pk * hv.w;
            }
        }
    }
    accO = acc; ZO = Z;
}

// Full warp-per-row aggregation from g_edges (deferred tail).
__device__ __forceinline__ void warp_agg_global(int row, float* __restrict__ out, int lane)
{
    const int   cnt  = g_cnt[row];
    const float a_si = g_as[row];
    const int*  erow = &g_edges[(size_t)row * MAX_E];
    float4 acc; float Z;
    warp_row_partial(cnt, a_si, [&](int k){ return erow[k]; }, lane, acc, Z);
    #pragma unroll
    for (int off = 16; off > 0; off >>= 1)
        Z += __shfl_xor_sync(0xffffffffu, Z, off);
    const float inv = 1.f / Z;
    float4 o;
    o.x = fmaxf(acc.x * inv, 0.f);
    o.y = fmaxf(acc.y * inv, 0.f);
    o.z = fmaxf(acc.z * inv, 0.f);
    o.w = fmaxf(acc.w * inv, 0.f);
    *reinterpret_cast<float4*>(&out[(size_t)row * D_OUT + lane * 4]) = o;
}

// ---------------------------------------------------------------------------
// Persistent TMA scan with INLINE aggregation of self-produced rows.
// 3-deep ring of 32KB smem row buffers; atomic-free ballot compaction into
// per-warp staging; tid0 scans counts and refills the slot IMMEDIATELY; then
// (if GEMM done) the block aggregates the row straight from staging — the
// TMA engine keeps streaming during aggregation. Pre-GEMM-done rows are
// deferred (edges persisted) and aggregated in a short tail.
// ---------------------------------------------------------------------------
__device__ __forceinline__ void scan_agg_rows(
    const float* __restrict__ adj, float* __restrict__ out, char* pool, int tid)
{
    float4* bufs    = reinterpret_cast<float4*>(pool);
    int*    s_stage = reinterpret_cast<int*>(pool + OFF_STAGE);   // [8][SEG_CAP]
    int*    ctl     = reinterpret_cast<int*>(pool + OFF_CTL);
    int*    s_defer = reinterpret_cast<int*>(pool + OFF_DEF);
    float*  s_part  = reinterpret_cast<float*>(pool + OFF_PART);  // [8][128]
    float*  s_Z     = reinterpret_cast<float*>(pool + OFF_Z);     // [8]
    const uint32_t mb0  = smem_u32(pool + OFF_MBAR);
    const uint32_t buf0 = smem_u32(pool);

    const int w     = tid >> 5;
    const unsigned lane  = tid & 31;
    const unsigned lmask = (1u << lane) - 1u;
    int* stage = s_stage + w * SEG_CAP;
    bool fenced = false;                        // per-thread acquire-once

    if (tid == 0) {
        ctl[CTL_GDONE] = 0;
        ctl[CTL_NDEF]  = 0;
        #pragma unroll
        for (int s = 0; s < S_DEPTH; s++)
            asm volatile("mbarrier.init.shared.b64 [%0], 1;" :: "r"(mb0 + 8u * s) : "memory");
    }
    __syncthreads();
    asm volatile("fence.proxy.async.shared::cta;" ::: "memory");

    // Prime the ring
    if (tid == 0) {
        #pragma unroll
        for (int s = 0; s < S_DEPTH; s++) {
            const int r = atomicAdd(&g_next, 1);
            ctl[CTL_ROW + s] = r;
            if (r < N_NODES) {
                asm volatile("mbarrier.arrive.expect_tx.shared.b64 _, [%0], %1;"
                             :: "r"(mb0 + 8u * s), "r"(ROW_BYTES) : "memory");
                asm volatile("cp.async.bulk.shared::cta.global.mbarrier::complete_tx::bytes "
                             "[%0], [%1], %2, [%3];"
                             :: "r"(buf0 + (uint32_t)s * ROW_BYTES),
                                "l"(adj + (size_t)r * N_NODES),
                                "r"(ROW_BYTES), "r"(mb0 + 8u * s) : "memory");
            }
        }
    }
    __syncthreads();

    int s = 0;
    unsigned parity = 0;
    while (true) {
        const int row = ctl[CTL_ROW + s];
        if (row >= N_NODES) break;              // block-uniform
        mbar_wait(mb0 + 8u * s, (parity >> s) & 1u);
        parity ^= (1u << s);

        // ---- atomic-free ballot extraction into warp staging ----
        const float4* B = bufs + s * (ROW_BYTES / 16);
        int wcnt = 0;
        #pragma unroll
        for (int it = 0; it < 8; it++) {
            const float4 q = B[it * 256 + tid];
            const int jb = (it * 256 + tid) * 4;
            #define COMP(val, off) {                                                   \
                const bool e = (val) != 0.f;                                           \
                const unsigned b = __ballot_sync(0xffffffffu, e);                      \
                if (e) { const int pi = wcnt + (int)__popc(b & lmask);                 \
                         if (pi < SEG_CAP) stage[pi] = jb + (off); }                   \
                wcnt += (int)__popc(b); }
            COMP(q.x, 0) COMP(q.y, 1) COMP(q.z, 2) COMP(q.w, 3)
            #undef COMP
        }
        if (wcnt > SEG_CAP) wcnt = SEG_CAP;
        if (lane == 0) ctl[CTL_WCNT + w] = wcnt;
        __syncthreads();                         // buf s free; counts visible

        // tid0: prefix counts, poll GEMM flag, refill slot s immediately
        if (tid == 0) {
            int t = 0;
            #pragma unroll
            for (int u = 0; u < 8; u++) { ctl[CTL_BASE + u] = t; t += ctl[CTL_WCNT + u]; }
            ctl[CTL_TOT] = t;

            if (!ctl[CTL_GDONE]) {
                if (*(volatile int*)&g_done == NB_GEMM) ctl[CTL_GDONE] = 1;
                else if (ctl[CTL_NDEF] >= DEF_CAP) {     // overflow fallback (rare)
                    while (*(volatile int*)&g_done < NB_GEMM) __nanosleep(64);
                    ctl[CTL_GDONE] = 1;
                }
            }
            if (!ctl[CTL_GDONE]) s_defer[ctl[CTL_NDEF]++] = row;

            const int r = atomicAdd(&g_next, 1);
            ctl[CTL_ROW + s] = r;
            if (r < N_NODES) {
                asm volatile("fence.proxy.async.shared::cta;" ::: "memory");
                asm volatile("mbarrier.arrive.expect_tx.shared.b64 _, [%0], %1;"
                             :: "r"(mb0 + 8u * s), "r"(ROW_BYTES) : "memory");
                asm volatile("cp.async.bulk.shared::cta.global.mbarrier::complete_tx::bytes "
                             "[%0], [%1], %2, [%3];"
                             :: "r"(buf0 + (uint32_t)s * ROW_BYTES),
                                "l"(adj + (size_t)r * N_NODES),
                                "r"(ROW_BYTES), "r"(mb0 + 8u * s) : "memory");
            }
        }
        __syncthreads();                         // bases + gdone + refill row visible

        if (ctl[CTL_GDONE]) {
            // ---- inline aggregation from warp staging (TMA streams on) ----
            if (!fenced) { __threadfence(); fenced = true; }   // acquire h/as/an
            const float a_si = g_as[row];
            float4 acc; float Z;
            warp_row_partial(wcnt, a_si, [&](int k){ return stage[k]; }, (int)lane, acc, Z);
            #pragma unroll
            for (int off = 16; off > 0; off >>= 1)
                Z += __shfl_xor_sync(0xffffffffu, Z, off);
            *reinterpret_cast<float4*>(&s_part[w * 128 + lane * 4]) = acc;
            if (lane == 0) s_Z[w] = Z;
            __syncthreads();
            if (tid < 128) {
                const float Zt = s_Z[0]+s_Z[1]+s_Z[2]+s_Z[3]+s_Z[4]+s_Z[5]+s_Z[6]+s_Z[7];
                const float inv = 1.f / Zt;
                float v = 0.f;
                #pragma unroll
                for (int u = 0; u < 8; u++) v += s_part[u * 128 + tid];
                out[(size_t)row * D_OUT + tid] = fmaxf(v * inv, 0.f);
            }
            __syncthreads();
        } else {
            // ---- defer: persist edge list for the tail ----
            const int base = ctl[CTL_BASE + w];
            for (int k = (int)lane; k < wcnt; k += 32)
                g_edges[(size_t)row * MAX_E + base + k] = stage[k];
            if (tid == 0) g_cnt[row] = ctl[CTL_TOT];
        }

        s = (s == S_DEPTH - 1) ? 0 : s + 1;
    }

    // ---- deferred tail: warp-per-row over this block's own deferred rows ----
    __syncthreads();
    const int nd = ctl[CTL_NDEF];
    if (nd > 0) {
        if (tid == 0 && !ctl[CTL_GDONE]) {
            while (*(volatile int*)&g_done < NB_GEMM) __nanosleep(64);
        }
        __syncthreads();
        __threadfence();
        for (int d = w; d < nd; d += 8)
            warp_agg_global(s_defer[d], out, (int)lane);
    }
}

// ---------------------------------------------------------------------------
// ONE kernel. Blocks [0,NB_GEMM): GEMM -> signal -> scan+agg.
// Blocks [NB_GEMM, NB_TOTAL): scan+agg from the start. One resident wave.
// ---------------------------------------------------------------------------
__global__ __launch_bounds__(256, 2) void fused_gat_kernel(
    const float* __restrict__ x, const float* __restrict__ adj,
    const float* __restrict__ W,
    const float* __restrict__ attn_s, const float* __restrict__ attn_n,
    float* __restrict__ out)
{
    extern __shared__ __align__(128) char pool[];   // SMEM_TOTAL bytes, unioned
    const int tid = threadIdx.x;

    if (blockIdx.x < NB_GEMM) {
        // ---------------- GEMM: 64x128 block tile, 8x4 per thread ---------
        typedef float AsT[32][64];
        typedef float BsT[32][128];
        AsT* As = reinterpret_cast<AsT*>(pool);            // 2 x 8 KB
        BsT* Bs = reinterpret_cast<BsT*>(pool + 16384);    // 2 x 16 KB

        const int ty = tid >> 5;
        const int tx = tid & 31;
        const int row0 = blockIdx.x * 64;

        float2 acc[8][2];
        #pragma unroll
        for (int r = 0; r < 8; r++) { acc[r][0] = make_float2(0.f,0.f); acc[r][1] = make_float2(0.f,0.f); }

        float4 aReg[2], bReg[4];

        #define LOAD_A(kt) do {                                                     \
            _Pragma("unroll")                                                       \
            for (int i = 0; i < 2; i++) {                                           \
                int f = tid + i * 256;                                              \
                int row = f >> 3, kq = f & 7;                                       \
                aReg[i] = *reinterpret_cast<const float4*>(                         \
                    &x[(size_t)(row0 + row) * D_IN + (kt) * 32 + kq * 4]);          \
            } } while (0)
        #define LOAD_B(kt) do {                                                     \
            _Pragma("unroll")                                                       \
            for (int i = 0; i < 4; i++) {                                           \
                int f = tid + i * 256;                                              \
                int kr = f >> 5, c4 = f & 31;                                       \
                bReg[i] = *reinterpret_cast<const float4*>(                         \
                    &W[(size_t)((kt) * 32 + kr) * D_OUT + c4 * 4]);                 \
            } } while (0)
        #define STORE_A(buf) do {                                                   \
            _Pragma("unroll")                                                       \
            for (int i = 0; i < 2; i++) {                                           \
                int f = tid + i * 256;                                              \
                int row = f >> 3, kq = f & 7;                                       \
                As[buf][kq * 4 + 0][row] = aReg[i].x;                               \
                As[buf][kq * 4 + 1][row] = aReg[i].y;                               \
                As[buf][kq * 4 + 2][row] = aReg[i].z;                               \
                As[buf][kq * 4 + 3][row] = aReg[i].w;                               \
            } } while (0)
        #define STORE_B(buf) do {                                                   \
            _Pragma("unroll")                                                       \
            for (int i = 0; i < 4; i++) {                                           \
                int f = tid + i * 256;                                              \
                int kr = f >> 5, c4 = f & 31;                                       \
                *reinterpret_cast<float4*>(&Bs[buf][kr][c4 * 4]) = bReg[i];         \
            } } while (0)

        LOAD_A(0); LOAD_B(0);
        STORE_A(0); STORE_B(0);
        __syncthreads();

        const int KT = D_IN / 32;  // 16
        for (int t = 0; t < KT; t++) {
            const int buf = t & 1;
            if (t + 1 < KT) { LOAD_A(t + 1); LOAD_B(t + 1); }
            #pragma unroll
            for (int k = 0; k < 32; k++) {
                float4 a0 = *reinterpret_cast<const float4*>(&As[buf][k][ty * 8]);
                float4 a1 = *reinterpret_cast<const float4*>(&As[buf][k][ty * 8 + 4]);
                float4 b  = *reinterpret_cast<const float4*>(&Bs[buf][k][tx * 4]);
                float  a[8]  = {a0.x, a0.y, a0.z, a0.w, a1.x, a1.y, a1.z, a1.w};
                float2 bb[2] = {{b.x, b.y}, {b.z, b.w}};
                #pragma unroll
                for (int r = 0; r < 8; r++) {
                    float2 a2 = make_float2(a[r], a[r]);
                    ffma2(acc[r][0], a2, bb[0]);
                    ffma2(acc[r][1], a2, bb[1]);
                }
            }
            if (t + 1 < KT) {
                __syncthreads();
                STORE_A(buf ^ 1); STORE_B(buf ^ 1);
                __syncthreads();
            }
        }

        // Epilogue: write h + fused a_s/a_n dots
        const int c0 = tx * 4;
        float ws[4], wn[4];
        #pragma unroll
        for (int q = 0; q < 4; q++) { ws[q] = attn_s[c0 + q]; wn[q] = attn_n[c0 + q]; }
        #pragma unroll
        for (int r = 0; r < 8; r++) {
            const int grow = row0 + ty * 8 + r;
            float4 o = make_float4(acc[r][0].x, acc[r][0].y, acc[r][1].x, acc[r][1].y);
            *reinterpret_cast<float4*>(&g_h[(size_t)grow * D_OUT + c0]) = o;
            float ds = o.x*ws[0] + o.y*ws[1] + o.z*ws[2] + o.w*ws[3];
            float dn = o.x*wn[0] + o.y*wn[1] + o.z*wn[2] + o.w*wn[3];
            #pragma unroll
            for (int off = 16; off > 0; off >>= 1) {
                ds += __shfl_down_sync(0xffffffffu, ds, off);
                dn += __shfl_down_sync(0xffffffffu, dn, off);
            }
            if (tx == 0) { g_as[grow] = ds; g_an[grow] = dn; }
        }

        // Release h/a_s/a_n, signal completion, join the scan pool.
        __threadfence();
        __syncthreads();
        if (tid == 0) atomicAdd(&g_done, 1);
        scan_agg_rows(adj, out, pool, tid);
    } else {
        scan_agg_rows(adj, out, pool, tid);
    }

    // Replay-safe reset: last block clears the work counters.
    __syncthreads();
    if (tid == 0) {
        const int old = atomicAdd(&g_fin, 1);
        if (old == NB_TOTAL - 1) { g_next = 0; g_done = 0; g_fin = 0; }
    }
}

// ---------------------------------------------------------------------------
extern "C" void kernel_launch(void* const* d_in, const int* in_sizes, int n_in,
                              void* d_out, int out_size)
{
    const float* x      = (const float*)d_in[0];  // [8192,512]
    const float* adj    = (const float*)d_in[1];  // [8192,8192]
    const float* W      = (const float*)d_in[2];  // [512,128]
    const float* attn_s = (const float*)d_in[3];  // [128,1]
    const float* attn_n = (const float*)d_in[4];  // [128,1]
    float* out = (float*)d_out;                    // [8192,128]

    cudaFuncSetAttribute(fused_gat_kernel,
                         cudaFuncAttributeMaxDynamicSharedMemorySize, SMEM_TOTAL);
    fused_gat_kernel<<<NB_TOTAL, 256, SMEM_TOTAL>>>(x, adj, W, attn_s, attn_n, out);
}

// round 16
// speedup vs baseline: 1.4294x; 1.4294x over previous
#include <cuda_runtime.h>
#include <cstdint>

#define N_NODES 8192
#define D_IN    512
#define D_OUT   128
#define LEAKY   0.2f
#define MAX_E   512
#define NB_GEMM 128     // GEMM blocks (64 rows each)
#define NB_SCAN 1024    // scan blocks (8 rows each), static assignment
#define ROWS_PER_SCAN 8

// Scratch (allocation-free: __device__ globals)
__device__ float g_h[N_NODES * D_OUT];        // 4 MB
__device__ float g_as[N_NODES];
__device__ float g_an[N_NODES];
__device__ int   g_edges[N_NODES * MAX_E];    // compacted edge lists
__device__ int   g_cnt[N_NODES];

// Packed dual-fp32 FMA (PTX f32x2, sm_100+): 2 FMAs per issue slot.
__device__ __forceinline__ void ffma2(float2& c, float2 a, float2 b) {
    asm("fma.rn.f32x2 %0, %1, %2, %0;"
        : "+l"(reinterpret_cast<unsigned long long&>(c))
        : "l"(reinterpret_cast<unsigned long long&>(a)),
          "l"(reinterpret_cast<unsigned long long&>(b)));
}

// ---------------------------------------------------------------------------
// Kernel A (heterogeneous, R5-exact): blocks [0,NB_GEMM) compute h = x@W
// (+ fused a_s/a_n projections). Blocks [NB_GEMM, NB_GEMM+NB_SCAN) are
// static 8-row scanners with register double-buffering: the next row's 8
// float4 loads are in flight while the current row is extracted. 4 waves of
// scan blocks keep fresh MLP bursts arriving at every wave transition.
// ---------------------------------------------------------------------------
__global__ __launch_bounds__(256, 2) void fused_gemm_scan_kernel(
    const float* __restrict__ x, const float* __restrict__ adj,
    const float* __restrict__ W,
    const float* __restrict__ attn_s, const float* __restrict__ attn_n)
{
    __shared__ __align__(16) char pool[49152];   // unioned: GEMM tiles | scan buffer
    const int tid = threadIdx.x;

    if (blockIdx.x < NB_GEMM) {
        // ---------------- GEMM path: 64x128 block tile, 8x4 per thread ----
        typedef float AsT[32][64];
        typedef float BsT[32][128];
        AsT* As = reinterpret_cast<AsT*>(pool);            // 2 x 8 KB
        BsT* Bs = reinterpret_cast<BsT*>(pool + 16384);    // 2 x 16 KB

        const int ty = tid >> 5;     // warp id 0..7 -> 8-row group
        const int tx = tid & 31;     // lane -> 4-col group
        const int row0 = blockIdx.x * 64;

        float2 acc[8][2];
        #pragma unroll
        for (int r = 0; r < 8; r++) { acc[r][0] = make_float2(0.f,0.f); acc[r][1] = make_float2(0.f,0.f); }

        float4 aReg[2], bReg[4];

        #define LOAD_A(kt) do {                                                     \
            _Pragma("unroll")                                                       \
            for (int i = 0; i < 2; i++) {                                           \
                int f = tid + i * 256;                                              \
                int row = f >> 3, kq = f & 7;                                       \
                aReg[i] = *reinterpret_cast<const float4*>(                         \
                    &x[(size_t)(row0 + row) * D_IN + (kt) * 32 + kq * 4]);          \
            } } while (0)
        #define LOAD_B(kt) do {                                                     \
            _Pragma("unroll")                                                       \
            for (int i = 0; i < 4; i++) {                                           \
                int f = tid + i * 256;                                              \
                int kr = f >> 5, c4 = f & 31;                                       \
                bReg[i] = *reinterpret_cast<const float4*>(                         \
                    &W[(size_t)((kt) * 32 + kr) * D_OUT + c4 * 4]);                 \
            } } while (0)
        #define STORE_A(buf) do {                                                   \
            _Pragma("unroll")                                                       \
            for (int i = 0; i < 2; i++) {                                           \
                int f = tid + i * 256;                                              \
                int row = f >> 3, kq = f & 7;                                       \
                As[buf][kq * 4 + 0][row] = aReg[i].x;                               \
                As[buf][kq * 4 + 1][row] = aReg[i].y;                               \
                As[buf][kq * 4 + 2][row] = aReg[i].z;                               \
                As[buf][kq * 4 + 3][row] = aReg[i].w;                               \
            } } while (0)
        #define STORE_B(buf) do {                                                   \
            _Pragma("unroll")                                                       \
            for (int i = 0; i < 4; i++) {                                           \
                int f = tid + i * 256;                                              \
                int kr = f >> 5, c4 = f & 31;                                       \
                *reinterpret_cast<float4*>(&Bs[buf][kr][c4 * 4]) = bReg[i];         \
            } } while (0)

        LOAD_A(0); LOAD_B(0);
        STORE_A(0); STORE_B(0);
        __syncthreads();

        const int KT = D_IN / 32;  // 16
        for (int t = 0; t < KT; t++) {
            const int buf = t & 1;
            if (t + 1 < KT) { LOAD_A(t + 1); LOAD_B(t + 1); }
            #pragma unroll
            for (int k = 0; k < 32; k++) {
                float4 a0 = *reinterpret_cast<const float4*>(&As[buf][k][ty * 8]);
                float4 a1 = *reinterpret_cast<const float4*>(&As[buf][k][ty * 8 + 4]);
                float4 b  = *reinterpret_cast<const float4*>(&Bs[buf][k][tx * 4]);
                float  a[8]  = {a0.x, a0.y, a0.z, a0.w, a1.x, a1.y, a1.z, a1.w};
                float2 bb[2] = {{b.x, b.y}, {b.z, b.w}};
                #pragma unroll
                for (int r = 0; r < 8; r++) {
                    float2 a2 = make_float2(a[r], a[r]);
                    ffma2(acc[r][0], a2, bb[0]);
                    ffma2(acc[r][1], a2, bb[1]);
                }
            }
            if (t + 1 < KT) {
                __syncthreads();
                STORE_A(buf ^ 1); STORE_B(buf ^ 1);
                __syncthreads();
            }
        }

        // Epilogue: write h + fused a_s/a_n dots (warp covers 8 rows x 128 cols)
        const int c0 = tx * 4;
        float ws[4], wn[4];
        #pragma unroll
        for (int q = 0; q < 4; q++) { ws[q] = attn_s[c0 + q]; wn[q] = attn_n[c0 + q]; }
        #pragma unroll
        for (int r = 0; r < 8; r++) {
            const int grow = row0 + ty * 8 + r;
            float4 o = make_float4(acc[r][0].x, acc[r][0].y, acc[r][1].x, acc[r][1].y);
            *reinterpret_cast<float4*>(&g_h[(size_t)grow * D_OUT + c0]) = o;
            float ds = o.x*ws[0] + o.y*ws[1] + o.z*ws[2] + o.w*ws[3];
            float dn = o.x*wn[0] + o.y*wn[1] + o.z*wn[2] + o.w*wn[3];
            #pragma unroll
            for (int off = 16; off > 0; off >>= 1) {
                ds += __shfl_down_sync(0xffffffffu, ds, off);
                dn += __shfl_down_sync(0xffffffffu, dn, off);
            }
            if (tx == 0) { g_as[grow] = ds; g_an[grow] = dn; }
        }
    } else {
        // ------------- Static scan: 8 rows, register double-buffered -------
        const int sb = blockIdx.x - NB_GEMM;       // 0..1023
        int* s_cnt = reinterpret_cast<int*>(pool);
        int* s_idx = s_cnt + 4;

        int row = sb;                               // rows sb, sb+1024, ...
        const float4* arow = reinterpret_cast<const float4*>(adj + (size_t)row * N_NODES);
        float4 cur[8], nxt[8];
        #pragma unroll
        for (int it = 0; it < 8; it++)
            cur[it] = __ldcs(arow + it * 256 + tid);

        for (int t = 0; t < ROWS_PER_SCAN; t++) {
            const int nrow = row + NB_SCAN;
            if (t + 1 < ROWS_PER_SCAN) {
                const float4* nr = reinterpret_cast<const float4*>(adj + (size_t)nrow * N_NODES);
                #pragma unroll
                for (int it = 0; it < 8; it++)
                    nxt[it] = __ldcs(nr + it * 256 + tid);    // in flight during extraction
            }
            if (tid == 0) s_cnt[0] = 0;
            __syncthreads();

            #pragma unroll
            for (int it = 0; it < 8; it++) {
                const float4 q = cur[it];
                const int jb = (it * 256 + tid) * 4;
                if (q.x != 0.f) { int p = atomicAdd(s_cnt, 1); if (p < MAX_E) s_idx[p] = jb; }
                if (q.y != 0.f) { int p = atomicAdd(s_cnt, 1); if (p < MAX_E) s_idx[p] = jb + 1; }
                if (q.z != 0.f) { int p = atomicAdd(s_cnt, 1); if (p < MAX_E) s_idx[p] = jb + 2; }
                if (q.w != 0.f) { int p = atomicAdd(s_cnt, 1); if (p < MAX_E) s_idx[p] = jb + 3; }
            }
            __syncthreads();
            const int cnt = min(s_cnt[0], MAX_E);
            for (int k = tid; k < cnt; k += 256)
                g_edges[(size_t)row * MAX_E + k] = s_idx[k];
            if (tid == 0) g_cnt[row] = cnt;
            __syncthreads();

            row = nrow;
            #pragma unroll
            for (int it = 0; it < 8; it++) cur[it] = nxt[it];
        }
    }
}

// ---------------------------------------------------------------------------
// Kernel B (R11/R14-exact): warp per row, one fused pass, no smem, no block
// barriers. Lanes compute 32 edges' softmax weights in parallel (coalesced
// index + g_an loads), then shuffle-broadcast (j, p) while all lanes gather
// h[j] (512B coalesced, L2-resident, 8-deep unrolled -> high MLP).
// No max-subtraction: logits are O(10), exp is fp32-safe; non-edges
// contribute exactly 0 in fp32, so edge-only softmax == dense reference.
// ---------------------------------------------------------------------------
__global__ __launch_bounds__(256) void aggregate_kernel(float* __restrict__ out)
{
    const int w    = threadIdx.x >> 5;
    const int lane = threadIdx.x & 31;
    const int i    = blockIdx.x * 8 + w;

    const int   cnt  = g_cnt[i];
    const float a_si = g_as[i];
    const int*  erow = &g_edges[(size_t)i * MAX_E];

    float4 acc = make_float4(0.f, 0.f, 0.f, 0.f);
    float  Z   = 0.f;

    for (int base = 0; base < cnt; base += 32) {
        int   myj = 0;
        float p   = 0.f;
        const int k = base + lane;
        if (k < cnt) {
            myj = erow[k];
            float e = a_si + g_an[myj];
            e = (e >= 0.f) ? e : LEAKY * e;
            p = __expf(e);
        }
        Z += p;
        const int m  = min(32, cnt - base);
        const int mp = (m + 7) & ~7;             // pad to 8; padded lanes have p=0
        for (int k0 = 0; k0 < mp; k0 += 8) {
            #pragma unroll
            for (int u = 0; u < 8; u++) {
                const int   j  = __shfl_sync(0xffffffffu, myj, k0 + u);
                const float pk = __shfl_sync(0xffffffffu, p,   k0 + u);
                const float4 hv = *reinterpret_cast<const float4*>(
                    &g_h[(size_t)j * D_OUT + lane * 4]);
                acc.x += pk * hv.x; acc.y += pk * hv.y;
                acc.z += pk * hv.z; acc.w += pk * hv.w;
            }
        }
    }
    #pragma unroll
    for (int off = 16; off > 0; off >>= 1)
        Z += __shfl_xor_sync(0xffffffffu, Z, off);
    const float inv = 1.f / Z;

    float4 o;
    o.x = fmaxf(acc.x * inv, 0.f);
    o.y = fmaxf(acc.y * inv, 0.f);
    o.z = fmaxf(acc.z * inv, 0.f);
    o.w = fmaxf(acc.w * inv, 0.f);
    *reinterpret_cast<float4*>(&out[(size_t)i * D_OUT + lane * 4]) = o;
}

// ---------------------------------------------------------------------------
extern "C" void kernel_launch(void* const* d_in, const int* in_sizes, int n_in,
                              void* d_out, int out_size)
{
    const float* x      = (const float*)d_in[0];  // [8192,512]
    const float* adj    = (const float*)d_in[1];  // [8192,8192]
    const float* W      = (const float*)d_in[2];  // [512,128]
    const float* attn_s = (const float*)d_in[3];  // [128,1]
    const float* attn_n = (const float*)d_in[4];  // [128,1]
    float* out = (float*)d_out;                    // [8192,128]

    fused_gemm_scan_kernel<<<NB_GEMM + NB_SCAN, 256>>>(x, adj, W, attn_s, attn_n);
    aggregate_kernel<<<N_NODES / 8, 256>>>(out);
}

// round 17
// speedup vs baseline: 1.7043x; 1.1924x over previous
#include <cuda_runtime.h>
#include <cstdint>

#define N_NODES 8192
#define D_IN    512
#define D_OUT   128
#define LEAKY   0.2f
#define MAX_E   512
#define NB_GEMM 128     // GEMM blocks (64 rows each)
#define NB_SCAN 1024    // scan blocks; each block = TWO 128-thread scan engines
#define ROWS_PER_GROUP 4

// Scratch (allocation-free: __device__ globals)
__device__ float g_h[N_NODES * D_OUT];        // 4 MB
__device__ float g_as[N_NODES];
__device__ float g_an[N_NODES];
__device__ int   g_edges[N_NODES * MAX_E];    // compacted edge lists
__device__ int   g_cnt[N_NODES];

// Packed dual-fp32 FMA (PTX f32x2, sm_100+): 2 FMAs per issue slot.
__device__ __forceinline__ void ffma2(float2& c, float2 a, float2 b) {
    asm("fma.rn.f32x2 %0, %1, %2, %0;"
        : "+l"(reinterpret_cast<unsigned long long&>(c))
        : "l"(reinterpret_cast<unsigned long long&>(a)),
          "l"(reinterpret_cast<unsigned long long&>(b)));
}

// ---------------------------------------------------------------------------
// Kernel A (heterogeneous): blocks [0,NB_GEMM) compute h = x@W (+ fused
// a_s/a_n projections) — unchanged from R16. Blocks [NB_GEMM, ...) are scan
// blocks, each split into TWO independent 128-thread groups with private
// row sequences, private smem, and group-scoped named barriers. Each group
// double-buffers 16KB half-rows in registers, so loads for the next half are
// in flight while the current half is extracted. Two concurrent extraction
// pipelines per block double the per-block consumption cadence that was
// capping DRAM at ~53%.
// ---------------------------------------------------------------------------
__global__ __launch_bounds__(256, 2) void fused_gemm_scan_kernel(
    const float* __restrict__ x, const float* __restrict__ adj,
    const float* __restrict__ W,
    const float* __restrict__ attn_s, const float* __restrict__ attn_n)
{
    __shared__ __align__(16) char pool[49152];   // unioned: GEMM tiles | scan buffers
    const int tid = threadIdx.x;

    if (blockIdx.x < NB_GEMM) {
        // ---------------- GEMM path: 64x128 block tile, 8x4 per thread ----
        typedef float AsT[32][64];
        typedef float BsT[32][128];
        AsT* As = reinterpret_cast<AsT*>(pool);            // 2 x 8 KB
        BsT* Bs = reinterpret_cast<BsT*>(pool + 16384);    // 2 x 16 KB

        const int ty = tid >> 5;     // warp id 0..7 -> 8-row group
        const int tx = tid & 31;     // lane -> 4-col group
        const int row0 = blockIdx.x * 64;

        float2 acc[8][2];
        #pragma unroll
        for (int r = 0; r < 8; r++) { acc[r][0] = make_float2(0.f,0.f); acc[r][1] = make_float2(0.f,0.f); }

        float4 aReg[2], bReg[4];

        #define LOAD_A(kt) do {                                                     \
            _Pragma("unroll")                                                       \
            for (int i = 0; i < 2; i++) {                                           \
                int f = tid + i * 256;                                              \
                int row = f >> 3, kq = f & 7;                                       \
                aReg[i] = *reinterpret_cast<const float4*>(                         \
                    &x[(size_t)(row0 + row) * D_IN + (kt) * 32 + kq * 4]);          \
            } } while (0)
        #define LOAD_B(kt) do {                                                     \
            _Pragma("unroll")                                                       \
            for (int i = 0; i < 4; i++) {                                           \
                int f = tid + i * 256;                                              \
                int kr = f >> 5, c4 = f & 31;                                       \
                bReg[i] = *reinterpret_cast<const float4*>(                         \
                    &W[(size_t)((kt) * 32 + kr) * D_OUT + c4 * 4]);                 \
            } } while (0)
        #define STORE_A(buf) do {                                                   \
            _Pragma("unroll")                                                       \
            for (int i = 0; i < 2; i++) {                                           \
                int f = tid + i * 256;                                              \
                int row = f >> 3, kq = f & 7;                                       \
                As[buf][kq * 4 + 0][row] = aReg[i].x;                               \
                As[buf][kq * 4 + 1][row] = aReg[i].y;                               \
                As[buf][kq * 4 + 2][row] = aReg[i].z;                               \
                As[buf][kq * 4 + 3][row] = aReg[i].w;                               \
            } } while (0)
        #define STORE_B(buf) do {                                                   \
            _Pragma("unroll")                                                       \
            for (int i = 0; i < 4; i++) {                                           \
                int f = tid + i * 256;                                              \
                int kr = f >> 5, c4 = f & 31;                                       \
                *reinterpret_cast<float4*>(&Bs[buf][kr][c4 * 4]) = bReg[i];         \
            } } while (0)

        LOAD_A(0); LOAD_B(0);
        STORE_A(0); STORE_B(0);
        __syncthreads();

        const int KT = D_IN / 32;  // 16
        for (int t = 0; t < KT; t++) {
            const int buf = t & 1;
            if (t + 1 < KT) { LOAD_A(t + 1); LOAD_B(t + 1); }
            #pragma unroll
            for (int k = 0; k < 32; k++) {
                float4 a0 = *reinterpret_cast<const float4*>(&As[buf][k][ty * 8]);
                float4 a1 = *reinterpret_cast<const float4*>(&As[buf][k][ty * 8 + 4]);
                float4 b  = *reinterpret_cast<const float4*>(&Bs[buf][k][tx * 4]);
                float  a[8]  = {a0.x, a0.y, a0.z, a0.w, a1.x, a1.y, a1.z, a1.w};
                float2 bb[2] = {{b.x, b.y}, {b.z, b.w}};
                #pragma unroll
                for (int r = 0; r < 8; r++) {
                    float2 a2 = make_float2(a[r], a[r]);
                    ffma2(acc[r][0], a2, bb[0]);
                    ffma2(acc[r][1], a2, bb[1]);
                }
            }
            if (t + 1 < KT) {
                __syncthreads();
                STORE_A(buf ^ 1); STORE_B(buf ^ 1);
                __syncthreads();
            }
        }

        // Epilogue: write h + fused a_s/a_n dots (warp covers 8 rows x 128 cols)
        const int c0 = tx * 4;
        float ws[4], wn[4];
        #pragma unroll
        for (int q = 0; q < 4; q++) { ws[q] = attn_s[c0 + q]; wn[q] = attn_n[c0 + q]; }
        #pragma unroll
        for (int r = 0; r < 8; r++) {
            const int grow = row0 + ty * 8 + r;
            float4 o = make_float4(acc[r][0].x, acc[r][0].y, acc[r][1].x, acc[r][1].y);
            *reinterpret_cast<float4*>(&g_h[(size_t)grow * D_OUT + c0]) = o;
            float ds = o.x*ws[0] + o.y*ws[1] + o.z*ws[2] + o.w*ws[3];
            float dn = o.x*wn[0] + o.y*wn[1] + o.z*wn[2] + o.w*wn[3];
            #pragma unroll
            for (int off = 16; off > 0; off >>= 1) {
                ds += __shfl_down_sync(0xffffffffu, ds, off);
                dn += __shfl_down_sync(0xffffffffu, dn, off);
            }
            if (tx == 0) { g_as[grow] = ds; g_an[grow] = dn; }
        }
    } else {
        // ------ Scan: two decoupled 128-thread engines per block -----------
        const int sb   = blockIdx.x - NB_GEMM;    // 0..1023
        const int g    = tid >> 7;                // group 0/1
        const int gtid = tid & 127;
        const int bid  = g + 1;                   // named barrier id (1 or 2)

        int* ibase = reinterpret_cast<int*>(pool);
        int* s_cnt = ibase + g;                   // one counter per group
        int* s_idx = ibase + 16 + g * MAX_E;      // [512] per group

        float4 cur[8], nxt[8];

        // group g covers rows sb + (2t+g)*1024, t = 0..3; each row = 2 halves
        // of 1024 float4 (8 per thread, 128 threads).
        #define LOADH(dst, hh) do {                                                  \
            const int _t = (hh) >> 1, _hf = (hh) & 1;                                \
            const float4* _p = reinterpret_cast<const float4*>(                      \
                adj + (size_t)(sb + (2*_t + g) * 1024) * N_NODES) + _hf*1024 + gtid; \
            _Pragma("unroll")                                                        \
            for (int it = 0; it < 8; it++) dst[it] = __ldcs(_p + it * 128);          \
        } while (0)

        LOADH(cur, 0);
        #pragma unroll 1
        for (int hh = 0; hh < 2 * ROWS_PER_GROUP; hh++) {
            const int t = hh >> 1, half = hh & 1;
            if (hh + 1 < 2 * ROWS_PER_GROUP) LOADH(nxt, hh + 1);   // in flight during extraction

            if (half == 0) {
                if (gtid == 0) *s_cnt = 0;
                asm volatile("bar.sync %0, 128;" :: "r"(bid) : "memory");
            }
            // extract this half (elements [half*4096, half*4096+4096))
            #pragma unroll
            for (int it = 0; it < 8; it++) {
                const float4 q = cur[it];
                const int jb = half * 4096 + (it * 128 + gtid) * 4;
                if (q.x != 0.f) { int p = atomicAdd(s_cnt, 1); if (p < MAX_E) s_idx[p] = jb; }
                if (q.y != 0.f) { int p = atomicAdd(s_cnt, 1); if (p < MAX_E) s_idx[p] = jb + 1; }
                if (q.z != 0.f) { int p = atomicAdd(s_cnt, 1); if (p < MAX_E) s_idx[p] = jb + 2; }
                if (q.w != 0.f) { int p = atomicAdd(s_cnt, 1); if (p < MAX_E) s_idx[p] = jb + 3; }
            }
            if (half == 1) {
                asm volatile("bar.sync %0, 128;" :: "r"(bid) : "memory");
                const int row = sb + (2 * t + g) * 1024;
                const int cnt = min(*s_cnt, MAX_E);
                for (int k = gtid; k < cnt; k += 128)
                    g_edges[(size_t)row * MAX_E + k] = s_idx[k];
                if (gtid == 0) g_cnt[row] = cnt;
                asm volatile("bar.sync %0, 128;" :: "r"(bid) : "memory");
            }
            #pragma unroll
            for (int it = 0; it < 8; it++) cur[it] = nxt[it];
        }
        #undef LOADH
    }
}

// ---------------------------------------------------------------------------
// Kernel B (unchanged, best measured): warp per row, one fused pass, no smem,
// no block barriers. Lanes compute 32 edges' softmax weights in parallel,
// then shuffle-broadcast (j, p) while all lanes gather h[j] (512B coalesced,
// L2-resident, 8-deep unrolled). No max-subtraction: logits are O(10), exp is
// fp32-safe; non-edges contribute exactly 0 in fp32, so edge-only softmax ==
// dense reference.
// ---------------------------------------------------------------------------
__global__ __launch_bounds__(256) void aggregate_kernel(float* __restrict__ out)
{
    const int w    = threadIdx.x >> 5;
    const int lane = threadIdx.x & 31;
    const int i    = blockIdx.x * 8 + w;

    const int   cnt  = g_cnt[i];
    const float a_si = g_as[i];
    const int*  erow = &g_edges[(size_t)i * MAX_E];

    float4 acc = make_float4(0.f, 0.f, 0.f, 0.f);
    float  Z   = 0.f;

    for (int base = 0; base < cnt; base += 32) {
        int   myj = 0;
        float p   = 0.f;
        const int k = base + lane;
        if (k < cnt) {
            myj = erow[k];
            float e = a_si + g_an[myj];
            e = (e >= 0.f) ? e : LEAKY * e;
            p = __expf(e);
        }
        Z += p;
        const int m  = min(32, cnt - base);
        const int mp = (m + 7) & ~7;             // pad to 8; padded lanes have p=0
        for (int k0 = 0; k0 < mp; k0 += 8) {
            #pragma unroll
            for (int u = 0; u < 8; u++) {
                const int   j  = __shfl_sync(0xffffffffu, myj, k0 + u);
                const float pk = __shfl_sync(0xffffffffu, p,   k0 + u);
                const float4 hv = *reinterpret_cast<const float4*>(
                    &g_h[(size_t)j * D_OUT + lane * 4]);
                acc.x += pk * hv.x; acc.y += pk * hv.y;
                acc.z += pk * hv.z; acc.w += pk * hv.w;
            }
        }
    }
    #pragma unroll
    for (int off = 16; off > 0; off >>= 1)
        Z += __shfl_xor_sync(0xffffffffu, Z, off);
    const float inv = 1.f / Z;

    float4 o;
    o.x = fmaxf(acc.x * inv, 0.f);
    o.y = fmaxf(acc.y * inv, 0.f);
    o.z = fmaxf(acc.z * inv, 0.f);
    o.w = fmaxf(acc.w * inv, 0.f);
    *reinterpret_cast<float4*>(&out[(size_t)i * D_OUT + lane * 4]) = o;
}

// ---------------------------------------------------------------------------
extern "C" void kernel_launch(void* const* d_in, const int* in_sizes, int n_in,
                              void* d_out, int out_size)
{
    const float* x      = (const float*)d_in[0];  // [8192,512]
    const float* adj    = (const float*)d_in[1];  // [8192,8192]
    const float* W      = (const float*)d_in[2];  // [512,128]
    const float* attn_s = (const float*)d_in[3];  // [128,1]
    const float* attn_n = (const float*)d_in[4];  // [128,1]
    float* out = (float*)d_out;                    // [8192,128]

    fused_gemm_scan_kernel<<<NB_GEMM + NB_SCAN, 256>>>(x, adj, W, attn_s, attn_n);
    aggregate_kernel<<<N_NODES / 8, 256>>>(out);
}